// round 15
// baseline (speedup 1.0000x reference)
#include <cuda_runtime.h>
#include <math.h>

// gdfn_region_batch:
//  A) copy_scan: warp-per-16x16-tile; copies light tiles (runs at LTS cap),
//     compacts heavy tile IDs into a global list.
//  B) heavy: GRIDB=760 (5 CTA/SM x 152 SM, forced via launch_bounds) so every
//     heavy tile gets a resident block in wave 1. exp-reduced math
//     (min_c exp(x) == exp(min_c x), bit-exact). P4 operands prefetched.
//     Self-resets counters for graph replay.

#define BATCH 8
#define CH 3
#define HH 512
#define WW 512
#define HP 514
#define TS 16
#define PR 22          // TS + 6
#define E2 20          // TS + 4
#define E1 18          // TS + 2
#define NTHREADS 256
#define TPB 32
#define NTILES (BATCH*TPB*TPB)   // 8192
#define GRIDA (NTILES/8)         // 1024 blocks, 8 warps = 8 tiles each
#define GRIDB 760                // 5 CTA/SM * 152 SM, one wave

#define SP_SIZE   (CH*PR*PR)   // 1452
#define SR_SIZE   (E2*E2)      // 400
#define SMOD_SIZE (E2*E2)      // 400
#define SMEM_FLOATS (SP_SIZE + SR_SIZE + SMOD_SIZE)  // 2252 floats = 9008 B

__device__ int g_count;          // zero-init; heavy kernel self-resets
__device__ int g_done;
__device__ int g_list[NTILES];

// ---------------------------------------------------------------------------
// Kernel A: warp-autonomous scan + copy; push heavy tiles.
// ---------------------------------------------------------------------------
__global__ __launch_bounds__(NTHREADS)
void copy_scan_kernel(const float* __restrict__ img,
                      const float* __restrict__ re_mask,
                      const int*   __restrict__ sel,
                      float* __restrict__ out)
{
    const int warp = threadIdx.x >> 5;
    const int lane = threadIdx.x & 31;
    const int tile = blockIdx.x * 8 + warp;

    const int b  = tile >> 10;
    const int h0 = ((tile >> 5) & 31) * TS;
    const int w0 = (tile & 31) * TS;

    const bool apply = (sel[b] != 0);

    size_t base[6];
    #pragma unroll
    for (int i = 0; i < 6; i++) {
        int idx = lane + 32 * i;
        int c   = idx >> 6;
        int rem = idx & 63;
        int r   = rem >> 2;
        int q   = rem & 3;
        base[i] = (((size_t)b * CH + c) * HH + (h0 + r)) * WW + w0 + q * 4;
    }

    bool light = true;
    if (apply) {
        int ok = 1;
        #pragma unroll
        for (int i = 0; i < 6; i++) {
            float4 rm = *(const float4*)(re_mask + base[i]);
            if (rm.x != 1.0f || rm.y != 1.0f || rm.z != 1.0f || rm.w != 1.0f)
                ok = 0;
        }
        light = __all_sync(0xffffffffu, ok);
    }

    if (light) {
        #pragma unroll
        for (int i = 0; i < 6; i++)
            *(float4*)(out + base[i]) = *(const float4*)(img + base[i]);
    } else if (lane == 0) {
        int slot = atomicAdd(&g_count, 1);
        g_list[slot] = tile;
    }
}

// ---------------------------------------------------------------------------
// Kernel B: heavy tiles; one resident block per tile (wave 1).
// ---------------------------------------------------------------------------
__global__ __launch_bounds__(NTHREADS, 5)
void heavy_kernel(const float* __restrict__ img,
                  const float* __restrict__ noise,
                  const float* __restrict__ re_mask,
                  const int*   __restrict__ mix_sel,
                  float* __restrict__ out)
{
    const int tid = threadIdx.x;
    const int cnt = g_count;

    extern __shared__ float smem[];
    float* sp   = smem;                    // [CH][PR][PR] img_p = pad(img)+noise
    float* sr   = sp + SP_SIZE;            // [E2][E2]     img_r
    float* smod = sr + SR_SIZE;            // [E2][E2]     img_3d_mod

    for (int hi = blockIdx.x; hi < cnt; hi += GRIDB) {
        __syncthreads();   // smem reuse guard across iterations
        const int tile = g_list[hi];
        const int b  = tile >> 10;
        const int h0 = ((tile >> 5) & 31) * TS;
        const int w0 = (tile & 31) * TS;

        // Prefetch phase-4 operands (independent of all smem phases):
        // this thread's output pixel, all 3 channels.
        const int ty4 = tid >> 4, tx4 = tid & 15;
        const size_t gidx0 = (((size_t)b * CH) * HH + (h0 + ty4)) * WW + (w0 + tx4);
        float pf_im[CH], pf_re[CH];
        #pragma unroll
        for (int c = 0; c < CH; c++) {
            pf_im[c] = img[gidx0 + (size_t)c * HH * WW];
            pf_re[c] = re_mask[gidx0 + (size_t)c * HH * WW];
        }

        // Phase 1: img_p region (pad(img)+noise)
        for (int i = tid; i < CH * PR * PR; i += NTHREADS) {
            int c   = i / (PR * PR);
            int rem = i % (PR * PR);
            int py  = rem / PR, px = rem % PR;
            int y = h0 - 2 + py;
            int x = w0 - 2 + px;
            float v = 0.0f;
            if (y >= 0 && y < HP && x >= 0 && x < HP) {
                v = noise[(((size_t)b * CH + c) * HP + y) * HP + x];
                int iy = y - 1, ix = x - 1;
                if (iy >= 0 && iy < HH && ix >= 0 && ix < WW)
                    v += img[(((size_t)b * CH + c) * HH + iy) * WW + ix];
            }
            sp[(c * PR + py) * PR + px] = v;
        }
        __syncthreads();

        const bool mix = (mix_sel[b] != 0);

        // Phase 2: img_r on E2 x E2.  m[k] = exp(-max_c(d^2*inv_c))
        // (bit-exact transform of min_c exp(-d^2*inv_c): exp is monotone).
        for (int p = tid; p < E2 * E2; p += NTHREADS) {
            int r  = p / E2, cc = p % E2;
            int gy = h0 - 2 + r, gx = w0 - 2 + cc;
            float img_r = 0.0f;
            if (gy >= 0 && gy < HH && gx >= 0 && gx < WW) {
                float t[9], vsum[9];
                #pragma unroll
                for (int k = 0; k < 9; k++) { t[k] = -3.4e38f; vsum[k] = 0.0f; }
                #pragma unroll
                for (int c = 0; c < CH; c++) {
                    float v[9]; float s = 0.0f;
                    #pragma unroll
                    for (int i = 0; i < 3; i++)
                        #pragma unroll
                        for (int j = 0; j < 3; j++) {
                            float tv = sp[(c * PR + r + i) * PR + cc + j];
                            v[i * 3 + j] = tv; s += tv; vsum[i * 3 + j] += tv;
                        }
                    float mean = s * (1.0f / 9.0f);
                    float sd2 = 0.0f;
                    #pragma unroll
                    for (int k = 0; k < 9; k++) {
                        float d = v[k] - mean; v[k] = d; sd2 += d * d;
                    }
                    float inv = __fdividef(4.0f, sd2);   // 1/(2*var_ddof1)
                    #pragma unroll
                    for (int k = 0; k < 9; k++)
                        t[k] = fmaxf(t[k], v[k] * v[k] * inv);
                }
                float num = 0.0f, den = 0.0f;
                #pragma unroll
                for (int k = 0; k < 9; k++) {
                    float m = __expf(-t[k]);
                    num += m * vsum[k]; den += m;
                }
                img_r = __fdividef(num, den);
            }
            sr[r * E2 + cc] = img_r;
        }
        __syncthreads();

        // Phase 3: argmin/argmax of img_r 3x3 (first-index tie-break);
        // recompute selected weight: exp(-max_c(d_sel^2*inv_c)), 1 exp.
        for (int p = tid; p < E1 * E1; p += NTHREADS) {
            int r  = 1 + p / E1, cc = 1 + p % E1;
            int gy = h0 - 2 + r, gx = w0 - 2 + cc;
            float mv = 0.0f;
            if (gy >= 0 && gy < HH && gx >= 0 && gx < WW) {
                float bmin = 3.4e38f, bmax = -3.4e38f;
                int kmin = 0, kmax = 0;
                #pragma unroll
                for (int i = 0; i < 3; i++)
                    #pragma unroll
                    for (int j = 0; j < 3; j++) {
                        float val = sr[(r - 1 + i) * E2 + (cc - 1 + j)];
                        int k = i * 3 + j;
                        if (val < bmin) { bmin = val; kmin = k; }
                        if (val > bmax) { bmax = val; kmax = k; }
                    }
                int id = mix ? kmax : kmin;
                int di = id / 3, dj = id % 3;
                float tmax = -3.4e38f;
                #pragma unroll
                for (int c = 0; c < CH; c++) {
                    float v[9]; float s = 0.0f;
                    #pragma unroll
                    for (int i = 0; i < 3; i++)
                        #pragma unroll
                        for (int j = 0; j < 3; j++) {
                            float tv = sp[(c * PR + r + i) * PR + cc + j];
                            v[i * 3 + j] = tv; s += tv;
                        }
                    float mean = s * (1.0f / 9.0f);
                    float sd2 = 0.0f;
                    #pragma unroll
                    for (int k = 0; k < 9; k++) {
                        float d = v[k] - mean; v[k] = d; sd2 += d * d;
                    }
                    float inv = __fdividef(4.0f, sd2);
                    float dsel = v[di * 3 + dj];
                    tmax = fmaxf(tmax, dsel * dsel * inv);
                }
                mv = __expf(-tmax);
            }
            smod[r * E2 + cc] = mv;
        }
        __syncthreads();

        // Phase 4: img_mod and final compose (256 px = 1 per thread)
        {
            float mm[9]; float den = 0.0f;
            #pragma unroll
            for (int i = 0; i < 3; i++)
                #pragma unroll
                for (int j = 0; j < 3; j++) {
                    float tv = smod[(ty4 + 1 + i) * E2 + (tx4 + 1 + j)];
                    mm[i * 3 + j] = tv; den += tv;
                }
            float rden = __fdividef(1.0f, den);
            #pragma unroll
            for (int c = 0; c < CH; c++) {
                float num = 0.0f;
                #pragma unroll
                for (int i = 0; i < 3; i++)
                    #pragma unroll
                    for (int j = 0; j < 3; j++)
                        num += sp[(c * PR + ty4 + 2 + i) * PR + tx4 + 2 + j] * mm[i * 3 + j];
                float imod = num * rden;
                float im = pf_im[c];
                float re = pf_re[c];
                out[gidx0 + (size_t)c * HH * WW] =
                    imod * (1.0f - re) + im * re;   // exact where re==1
            }
        }
    }

    // Self-reset for next replay: last-finishing block zeroes the counters.
    __syncthreads();
    if (tid == 0) {
        __threadfence();
        int old = atomicAdd(&g_done, 1);
        if (old == GRIDB - 1) { g_count = 0; g_done = 0; }
    }
}

extern "C" void kernel_launch(void* const* d_in, const int* in_sizes, int n_in,
                              void* d_out, int out_size)
{
    const float* img     = (const float*)d_in[0];
    const float* noise   = (const float*)d_in[1];
    const float* re_mask = (const float*)d_in[2];
    const int*   sel     = (const int*)d_in[3];
    const int*   mix_sel = (const int*)d_in[4];
    float* out = (float*)d_out;

    size_t smem = SMEM_FLOATS * sizeof(float);
    cudaFuncSetAttribute(heavy_kernel,
                         cudaFuncAttributeMaxDynamicSharedMemorySize, (int)smem);

    copy_scan_kernel<<<GRIDA, NTHREADS>>>(img, re_mask, sel, out);
    heavy_kernel<<<GRIDB, NTHREADS, smem>>>(img, noise, re_mask, mix_sel, out);
}